// round 5
// baseline (speedup 1.0000x reference)
#include <cuda_runtime.h>
#include <cuda_bf16.h>

#define BATCH 16
#define CIN   256
#define HW    4096
#define DDIM  128
#define CCL   32
#define EPSV  1e-8f
#define NF    ((long)BATCH * CIN * HW)

#define KC    32
#define NCH   8

// smem layout (bytes): row pitch 20 u32 (80B) per 128-row operand pane
#define OFF_AHI 0
#define OFF_ALO 10240
#define OFF_BHI 20480
#define OFF_BLO 30720
#define OFF_ZC  40960
#define OFF_BIAS 41472
#define SMEM_BYTES 41984

__device__ float g_kld[BATCH];
__device__ int   g_cnt;

// ---------------------------------------------------------------------------
__device__ __forceinline__ unsigned smem_u32(const void* p) {
    unsigned a;
    asm("{ .reg .u64 t; cvta.to.shared.u64 t, %1; cvt.u32.u64 %0, t; }" : "=r"(a) : "l"(p));
    return a;
}
__device__ __forceinline__ unsigned lds32(unsigned a) {
    unsigned v;
    asm volatile("ld.shared.b32 %0, [%1];" : "=r"(v) : "r"(a));
    return v;
}
#define STS128(a, r0, r1, r2, r3) \
    asm volatile("st.shared.v4.b32 [%0], {%1,%2,%3,%4};" :: "r"(a), "r"(r0), "r"(r1), "r"(r2), "r"(r3) : "memory")

// exact split of two fp32 into bf16x2 hi (truncated) + bf16x2 lo (residual)
__device__ __forceinline__ void split2(float a, float b, unsigned& hi, unsigned& lo) {
    unsigned ua = __float_as_uint(a), ub = __float_as_uint(b);
    hi = __byte_perm(ua, ub, 0x7632);
    float alo = a - __uint_as_float(ua & 0xFFFF0000u);
    float blo = b - __uint_as_float(ub & 0xFFFF0000u);
    asm("cvt.rn.bf16x2.f32 %0, %1, %2;" : "=r"(lo) : "f"(blo), "f"(alo));
}

__device__ __forceinline__ void mma_bf16(float* c, unsigned a0, unsigned a1,
                                         unsigned a2, unsigned a3,
                                         unsigned b0, unsigned b1) {
    asm volatile(
        "mma.sync.aligned.m16n8k16.row.col.f32.bf16.bf16.f32 "
        "{%0,%1,%2,%3}, {%4,%5,%6,%7}, {%8,%9}, {%0,%1,%2,%3};"
        : "+f"(c[0]), "+f"(c[1]), "+f"(c[2]), "+f"(c[3])
        : "r"(a0), "r"(a1), "r"(a2), "r"(a3), "r"(b0), "r"(b1));
}

// ---------------------------------------------------------------------------
// Single fused kernel.
//   blocks 0..15         : per-batch KLD + scalar tail of out
//   blocks 16..1039      : GEMM tiles (b 16 x p-tile 32 x o-half 2), inline bias
// ---------------------------------------------------------------------------
__global__ __launch_bounds__(256, 2)
void fused_kernel(const float* __restrict__ f,  const float* __restrict__ mu_prior,
                  const float* __restrict__ ls_prior, const float* __restrict__ pi_prior,
                  const float* __restrict__ mu_post,  const float* __restrict__ ls_post,
                  const float* __restrict__ noise_c,  const float* __restrict__ noise_z,
                  const float* __restrict__ W,        const float* __restrict__ pb,
                  float* __restrict__ out, int out_size)
{
    __shared__ __align__(16) char smem[SMEM_BYTES];
    const int t = threadIdx.x;
    const int wid = t >> 5, lane = t & 31;

    if (blockIdx.x < 16) {
        // ------------------------- KLD blocks -------------------------
        const int b = blockIdx.x;
        float* S = (float*)smem;
        float* zpost = S;        float* mupo = S + 128;  float* lspo = S + 256;
        float* e2po  = S + 384;  float* kstd = S + 512;
        float* lps   = S + 640;  float* klgs = S + 896;
        if (t < DDIM) {
            float mu = mu_post[b * DDIM + t];
            float ls = ls_post[b * DDIM + t];
            float e  = expf(ls);
            mupo[t] = mu; lspo[t] = ls; e2po[t] = e * e;
            zpost[t] = mu + e * noise_c[b * DDIM + t];
            kstd[t]  = -ls + 0.5f * (e * e + mu * mu) - 0.5f;
        }
        __syncthreads();
        const int c = lane;
        float lp = 0.f, klg = 0.f;
        #pragma unroll 4
        for (int j = 0; j < 16; j++) {
            int dd = wid * 16 + j;
            long idx = ((long)b * DDIM + dd) * CCL + c;
            float mpr = mu_prior[idx];
            float lpr = ls_prior[idx];
            float s2x2 = 2.f * expf(2.f * lpr);
            float dz = zpost[dd] - mpr;
            lp += -lpr - 0.91893853320467274f - dz * dz / s2x2;
            float dm = mupo[dd] - mpr;
            klg += lpr - lspo[dd] + (e2po[dd] + dm * dm) / (s2x2 + EPSV) - 0.5f;
        }
        lps[wid * 32 + c] = lp; klgs[wid * 32 + c] = klg;
        __syncthreads();
        if (wid == 0) {
            float LP = 0.f, KG = 0.f;
            #pragma unroll
            for (int j = 0; j < 8; j++) { LP += lps[j * 32 + c]; KG += klgs[j * 32 + c]; }
            float m = LP;
            #pragma unroll
            for (int o = 16; o; o >>= 1) m = fmaxf(m, __shfl_xor_sync(~0u, m, o));
            float e = expf(LP - m), s = e;
            #pragma unroll
            for (int o = 16; o; o >>= 1) s += __shfl_xor_sync(~0u, s, o);
            float pi = e / s;
            float term = pi * KG + pi * (logf(pi + EPSV) - logf(pi_prior[b * CCL + c] + EPSV));
            #pragma unroll
            for (int o = 16; o; o >>= 1) term += __shfl_xor_sync(~0u, term, o);
            float ks = kstd[c] + kstd[c + 32] + kstd[c + 64] + kstd[c + 96];
            #pragma unroll
            for (int o = 16; o; o >>= 1) ks += __shfl_xor_sync(~0u, ks, o);
            if (c == 0) g_kld[b] = term + ks;
        }
        __syncthreads();
        if (t == 0) {
            __threadfence();
            int old = atomicAdd(&g_cnt, 1);
            if (old == BATCH - 1) {
                __threadfence();
                float s = 0.f;
                #pragma unroll
                for (int bb = 0; bb < BATCH; bb++) s += g_kld[bb];
                s *= (1.f / BATCH);
                for (long i = NF; i < (long)out_size; i++) out[i] = s;
                atomicExch(&g_cnt, 0);
            }
        }
        return;
    }

    // ------------------------------ GEMM blocks ------------------------------
    const int gbid = blockIdx.x - 16;
    const int b  = gbid >> 6;
    const int oh = gbid & 1;                 // o-half twins adjacent -> L2 reuse of f
    const int pt = (gbid >> 1) & 31;
    const int o0 = oh << 7, p0 = pt << 7;

    const unsigned sb = smem_u32(smem);
    float* zc    = (float*)(smem + OFF_ZC);
    float* sbias = (float*)(smem + OFF_BIAS);

    // --- zc + per-CTA bias (tiny; W cols 256..383 are L2-hot) ---
    if (t < DDIM) {
        float mu = mu_post[b * DDIM + t];
        float ls = ls_post[b * DDIM + t];
        zc[t] = mu + (expf(ls) + EPSV) * noise_z[b * DDIM + t];
    }
    __syncthreads();
    if (t < 128) {
        float acc = 0.f;
        const float* wz = W + (long)(o0 + t) * 384 + CIN;
        #pragma unroll
        for (int dd = 0; dd < DDIM; dd += 4) {
            float4 wv = *(const float4*)(wz + dd);
            acc += wv.x * zc[dd] + wv.y * zc[dd + 1] + wv.z * zc[dd + 2] + wv.w * zc[dd + 3];
        }
        sbias[t] = acc + pb[o0 + t];
    }

    const int pidx = t & 127;                // row within pane (p for B, o for A)
    const int cg   = t >> 7;                 // k half: 0 or 1 (8 kpairs each)
    const float* fbase = f + (long)b * CIN * HW + p0 + pidx;
    const float* wbase = W + (long)(o0 + pidx) * 384 + cg * 16;

    float rfF[16], rfW[16];
    // prefetch chunk 0
    #pragma unroll
    for (int j = 0; j < 8; j++) {
        int kp = cg * 8 + j;
        rfF[2 * j]     = fbase[(long)(2 * kp) * HW];
        rfF[2 * j + 1] = fbase[(long)(2 * kp + 1) * HW];
    }
    #pragma unroll
    for (int j = 0; j < 4; j++)
        *(float4*)&rfW[4 * j] = *(const float4*)(wbase + 4 * j);

    float c[2][8][4];
    #pragma unroll
    for (int i = 0; i < 2; i++)
        #pragma unroll
        for (int j = 0; j < 8; j++)
            #pragma unroll
            for (int k = 0; k < 4; k++) c[i][j][k] = 0.f;

    const int wy = wid >> 1;                 // o block (32 each)
    const int wx = wid & 1;                  // p block (64 each)
    const unsigned r = lane >> 2, qq = lane & 3;
    const unsigned aoff = ((wy * 32 + r) * 20 + qq) * 4;
    const unsigned boff = ((wx * 64 + r) * 20 + qq) * 4;

    for (int ch = 0; ch < NCH; ch++) {
        __syncthreads();                     // prev MMA done -> panes free

        // convert W chunk -> A panes
        {
            unsigned hw[8], lw[8];
            #pragma unroll
            for (int j = 0; j < 8; j++) split2(rfW[2 * j], rfW[2 * j + 1], hw[j], lw[j]);
            unsigned so = (unsigned)(pidx * 20 + cg * 8) * 4;
            STS128(sb + OFF_AHI + so,      hw[0], hw[1], hw[2], hw[3]);
            STS128(sb + OFF_AHI + so + 16, hw[4], hw[5], hw[6], hw[7]);
            STS128(sb + OFF_ALO + so,      lw[0], lw[1], lw[2], lw[3]);
            STS128(sb + OFF_ALO + so + 16, lw[4], lw[5], lw[6], lw[7]);
        }
        // convert f chunk -> B panes
        {
            unsigned hw[8], lw[8];
            #pragma unroll
            for (int j = 0; j < 8; j++) split2(rfF[2 * j], rfF[2 * j + 1], hw[j], lw[j]);
            unsigned so = (unsigned)(pidx * 20 + cg * 8) * 4;
            STS128(sb + OFF_BHI + so,      hw[0], hw[1], hw[2], hw[3]);
            STS128(sb + OFF_BHI + so + 16, hw[4], hw[5], hw[6], hw[7]);
            STS128(sb + OFF_BLO + so,      lw[0], lw[1], lw[2], lw[3]);
            STS128(sb + OFF_BLO + so + 16, lw[4], lw[5], lw[6], lw[7]);
        }
        __syncthreads();                     // panes ready

        if (ch < NCH - 1) {                  // register prefetch chunk ch+1
            const float* fc = fbase + (long)((ch + 1) * KC) * HW;
            #pragma unroll
            for (int j = 0; j < 8; j++) {
                int kp = cg * 8 + j;
                rfF[2 * j]     = fc[(long)(2 * kp) * HW];
                rfF[2 * j + 1] = fc[(long)(2 * kp + 1) * HW];
            }
            const float* wc = wbase + (ch + 1) * KC;
            #pragma unroll
            for (int j = 0; j < 4; j++)
                *(float4*)&rfW[4 * j] = *(const float4*)(wc + 4 * j);
        }

        // MMA phase: 3 passes (AhiBhi, AhiBlo, AloBhi) x 2 k-slices x 16 mma
        #pragma unroll
        for (int pr = 0; pr < 3; pr++) {
            const unsigned Ab = sb + ((pr == 2) ? OFF_ALO : OFF_AHI) + aoff;
            const unsigned Bb = sb + ((pr == 1) ? OFF_BLO : OFF_BHI) + boff;
            #pragma unroll
            for (int ks = 0; ks < 2; ks++) {
                unsigned b0[8], b1[8];
                #pragma unroll
                for (int ni = 0; ni < 8; ni++) {
                    unsigned ad = Bb + ks * 32 + ni * 640;
                    b0[ni] = lds32(ad);
                    b1[ni] = lds32(ad + 16);
                }
                #pragma unroll
                for (int mi = 0; mi < 2; mi++) {
                    unsigned aad = Ab + ks * 32 + mi * 1280;
                    unsigned a0 = lds32(aad);
                    unsigned a1 = lds32(aad + 640);
                    unsigned a2 = lds32(aad + 16);
                    unsigned a3 = lds32(aad + 656);
                    #pragma unroll
                    for (int ni = 0; ni < 8; ni++)
                        mma_bf16(c[mi][ni], a0, a1, a2, a3, b0[ni], b1[ni]);
                }
            }
        }
    }

    // ---- epilogue: bias add + store (32B-sector aligned pairs) ----
    #pragma unroll
    for (int mi = 0; mi < 2; mi++) {
        #pragma unroll
        for (int h = 0; h < 2; h++) {
            int ol = wy * 32 + mi * 16 + h * 8 + (int)r;
            float bias = sbias[ol];
            float* row = out + ((long)(b * CIN + o0 + ol)) * HW + p0 + wx * 64 + 2 * qq;
            #pragma unroll
            for (int ni = 0; ni < 8; ni++) {
                float2 v = make_float2(c[mi][ni][2 * h] + bias,
                                       c[mi][ni][2 * h + 1] + bias);
                *(float2*)(row + ni * 8) = v;
            }
        }
    }
}

// ---------------------------------------------------------------------------
extern "C" void kernel_launch(void* const* d_in, const int* in_sizes, int n_in,
                              void* d_out, int out_size)
{
    const float* f_curr   = (const float*)d_in[0];
    const float* mu_prior = (const float*)d_in[1];
    const float* ls_prior = (const float*)d_in[2];
    const float* pi_prior = (const float*)d_in[3];
    const float* mu_post  = (const float*)d_in[4];
    const float* ls_post  = (const float*)d_in[5];
    const float* noise_c  = (const float*)d_in[6];
    const float* noise_z  = (const float*)d_in[7];
    const float* W        = (const float*)d_in[8];
    const float* pb       = (const float*)d_in[9];
    float* out = (float*)d_out;

    fused_kernel<<<16 + 1024, 256>>>(f_curr, mu_prior, ls_prior, pi_prior,
                                     mu_post, ls_post, noise_c, noise_z,
                                     W, pb, out, out_size);
}

// round 6
// speedup vs baseline: 1.1197x; 1.1197x over previous
#include <cuda_runtime.h>
#include <cuda_bf16.h>

#define BATCH 16
#define CIN   256
#define HW    4096
#define DDIM  128
#define CCL   32
#define EPSV  1e-8f
#define NF    ((long)BATCH * CIN * HW)

#define KC    32
#define NCH   8
#define GEMM_BLKS 512     // 16 b x 32 p-tiles, O=256 full per CTA

// ---- smem layout (bytes) ----
#define OFF_STG   0                   // 2 x (32 rows x 528B) f staging
#define STG_BUF   16896
#define OFF_PANE  33792               // 2 x 61440 operand panes
#define PANE_BUF  61440
#define PA_HI     0                   // 256 rows x 80B
#define PA_LO     20480
#define PB_HI     40960               // 128 rows x 80B
#define PB_LO     51200
#define OFF_ZC    156672
#define OFF_BIAS  157184
#define SMEM_TOTAL 158208

__device__ float g_kld[BATCH];
__device__ int   g_cnt;

// ---------------------------------------------------------------------------
__device__ __forceinline__ unsigned smem_u32(const void* p) {
    unsigned a;
    asm("{ .reg .u64 t; cvta.to.shared.u64 t, %1; cvt.u32.u64 %0, t; }" : "=r"(a) : "l"(p));
    return a;
}
__device__ __forceinline__ void cp16(unsigned dst, const void* src) {
    asm volatile("cp.async.cg.shared.global [%0], [%1], 16;" :: "r"(dst), "l"(src));
}
#define CP_COMMIT() asm volatile("cp.async.commit_group;")
#define CP_WAIT(n)  asm volatile("cp.async.wait_group %0;" :: "n"(n))

__device__ __forceinline__ unsigned lds32(unsigned a) {
    unsigned v;
    asm volatile("ld.shared.b32 %0, [%1];" : "=r"(v) : "r"(a));
    return v;
}
#define STS128(a, r0, r1, r2, r3) \
    asm volatile("st.shared.v4.b32 [%0], {%1,%2,%3,%4};" :: "r"(a), "r"(r0), "r"(r1), "r"(r2), "r"(r3) : "memory")

// exact split of two fp32 into bf16x2 hi (truncated) + bf16x2 lo (residual)
__device__ __forceinline__ void split2(float a, float b, unsigned& hi, unsigned& lo) {
    unsigned ua = __float_as_uint(a), ub = __float_as_uint(b);
    hi = __byte_perm(ua, ub, 0x7632);
    float alo = a - __uint_as_float(ua & 0xFFFF0000u);
    float blo = b - __uint_as_float(ub & 0xFFFF0000u);
    asm("cvt.rn.bf16x2.f32 %0, %1, %2;" : "=r"(lo) : "f"(blo), "f"(alo));
}

__device__ __forceinline__ void mma_bf16(float* c, unsigned a0, unsigned a1,
                                         unsigned a2, unsigned a3,
                                         unsigned b0, unsigned b1) {
    asm volatile(
        "mma.sync.aligned.m16n8k16.row.col.f32.bf16.bf16.f32 "
        "{%0,%1,%2,%3}, {%4,%5,%6,%7}, {%8,%9}, {%0,%1,%2,%3};"
        : "+f"(c[0]), "+f"(c[1]), "+f"(c[2]), "+f"(c[3])
        : "r"(a0), "r"(a1), "r"(a2), "r"(a3), "r"(b0), "r"(b1));
}

// ---------------------------------------------------------------------------
// Single fused kernel: blocks 0..511 GEMM, blocks 512..527 KLD.
// ---------------------------------------------------------------------------
__global__ __launch_bounds__(512, 1)
void fused_kernel(const float* __restrict__ f,  const float* __restrict__ mu_prior,
                  const float* __restrict__ ls_prior, const float* __restrict__ pi_prior,
                  const float* __restrict__ mu_post,  const float* __restrict__ ls_post,
                  const float* __restrict__ noise_c,  const float* __restrict__ noise_z,
                  const float* __restrict__ W,        const float* __restrict__ pb,
                  float* __restrict__ out, int out_size)
{
    extern __shared__ __align__(16) char smem[];
    const int t = threadIdx.x;
    const int wid = t >> 5, lane = t & 31;

    if (blockIdx.x >= GEMM_BLKS) {
        // ------------------------- KLD blocks -------------------------
        const int b = blockIdx.x - GEMM_BLKS;
        float* S = (float*)smem;
        float* zpost = S;        float* mupo = S + 128;  float* lspo = S + 256;
        float* e2po  = S + 384;  float* kstd = S + 512;
        float* lps   = S + 640;  float* klgs = S + 896;
        if (t < DDIM) {
            float mu = mu_post[b * DDIM + t];
            float ls = ls_post[b * DDIM + t];
            float e  = expf(ls);
            mupo[t] = mu; lspo[t] = ls; e2po[t] = e * e;
            zpost[t] = mu + e * noise_c[b * DDIM + t];
            kstd[t]  = -ls + 0.5f * (e * e + mu * mu) - 0.5f;
        }
        __syncthreads();
        const int c = lane;
        if (wid < 8) {
            float lp = 0.f, klg = 0.f;
            #pragma unroll 4
            for (int j = 0; j < 16; j++) {
                int dd = wid * 16 + j;
                long idx = ((long)b * DDIM + dd) * CCL + c;
                float mpr = mu_prior[idx];
                float lpr = ls_prior[idx];
                float s2x2 = 2.f * expf(2.f * lpr);
                float dz = zpost[dd] - mpr;
                lp += -lpr - 0.91893853320467274f - dz * dz / s2x2;
                float dm = mupo[dd] - mpr;
                klg += lpr - lspo[dd] + (e2po[dd] + dm * dm) / (s2x2 + EPSV) - 0.5f;
            }
            lps[wid * 32 + c] = lp; klgs[wid * 32 + c] = klg;
        }
        __syncthreads();
        if (wid == 0) {
            float LP = 0.f, KG = 0.f;
            #pragma unroll
            for (int j = 0; j < 8; j++) { LP += lps[j * 32 + c]; KG += klgs[j * 32 + c]; }
            float m = LP;
            #pragma unroll
            for (int o = 16; o; o >>= 1) m = fmaxf(m, __shfl_xor_sync(~0u, m, o));
            float e = expf(LP - m), s = e;
            #pragma unroll
            for (int o = 16; o; o >>= 1) s += __shfl_xor_sync(~0u, s, o);
            float pi = e / s;
            float term = pi * KG + pi * (logf(pi + EPSV) - logf(pi_prior[b * CCL + c] + EPSV));
            #pragma unroll
            for (int o = 16; o; o >>= 1) term += __shfl_xor_sync(~0u, term, o);
            float ks = kstd[c] + kstd[c + 32] + kstd[c + 64] + kstd[c + 96];
            #pragma unroll
            for (int o = 16; o; o >>= 1) ks += __shfl_xor_sync(~0u, ks, o);
            if (c == 0) g_kld[b] = term + ks;
        }
        __syncthreads();
        if (t == 0) {
            __threadfence();
            int old = atomicAdd(&g_cnt, 1);
            if (old == BATCH - 1) {
                __threadfence();
                float s = 0.f;
                #pragma unroll
                for (int bb = 0; bb < BATCH; bb++) s += g_kld[bb];
                s *= (1.f / BATCH);
                for (long i = NF; i < (long)out_size; i++) out[i] = s;
                atomicExch(&g_cnt, 0);
            }
        }
        return;
    }

    // ------------------------------ GEMM blocks ------------------------------
    const int b  = blockIdx.x >> 5;
    const int p0 = (blockIdx.x & 31) << 7;
    const unsigned sb = smem_u32(smem);
    float* zc    = (float*)(smem + OFF_ZC);
    float* sbias = (float*)(smem + OFF_BIAS);

    const float* fb = f + (long)b * CIN * HW + p0;
    const int ow   = t >> 1;              // W row handled by this thread
    const int wh   = (t & 1) * 16;        // k sub-half (16 floats)
    const float* wbase = W + (long)ow * 384 + wh;

    // f staging issue for chunk ch -> stg[par]
    auto issue_f = [&](int ch, int par) {
        unsigned stg = sb + OFF_STG + par * STG_BUF;
        #pragma unroll
        for (int j = 0; j < 2; j++) {
            int id = t + j * 512, row = id >> 5, seg = id & 31;
            cp16(stg + row * 528 + seg * 16, fb + (long)(ch * KC + row) * HW + seg * 4);
        }
        CP_COMMIT();
    };

    float rfW[16];
    auto load_w = [&](int ch) {
        const float* wc = wbase + ch * KC;
        #pragma unroll
        for (int j = 0; j < 4; j++) *(float4*)&rfW[4 * j] = *(const float4*)(wc + 4 * j);
    };

    // convert current rfW + staged f chunk into pane[par]
    auto convert = [&](int par) {
        const unsigned pane = sb + OFF_PANE + par * PANE_BUF;
        {   // W -> A panes: row ow, kpairs wh/2 .. +7
            unsigned hw[8], lw[8];
            #pragma unroll
            for (int j = 0; j < 8; j++) split2(rfW[2 * j], rfW[2 * j + 1], hw[j], lw[j]);
            unsigned so = (unsigned)(ow * 20 + (wh >> 1)) * 4;
            STS128(pane + PA_HI + so,      hw[0], hw[1], hw[2], hw[3]);
            STS128(pane + PA_HI + so + 16, hw[4], hw[5], hw[6], hw[7]);
            STS128(pane + PA_LO + so,      lw[0], lw[1], lw[2], lw[3]);
            STS128(pane + PA_LO + so + 16, lw[4], lw[5], lw[6], lw[7]);
        }
        {   // f (staged) -> B panes: transpose + split
            const float* stg = (const float*)(smem + OFF_STG + par * STG_BUF);
            const int p = t & 127, g = t >> 7;       // g: 0..3 -> 4 kpairs each
            unsigned hw[4], lw[4];
            #pragma unroll
            for (int j = 0; j < 4; j++) {
                int kp = g * 4 + j;
                split2(stg[(2 * kp) * 132 + p], stg[(2 * kp + 1) * 132 + p], hw[j], lw[j]);
            }
            unsigned so = (unsigned)(p * 20 + g * 4) * 4;
            STS128(pane + PB_HI + so, hw[0], hw[1], hw[2], hw[3]);
            STS128(pane + PB_LO + so, lw[0], lw[1], lw[2], lw[3]);
        }
    };

    // ---- prologue ----
    issue_f(0, 0);
    issue_f(1, 1);
    load_w(0);
    if (t < DDIM) {
        float mu = mu_post[b * DDIM + t];
        float ls = ls_post[b * DDIM + t];
        zc[t] = mu + (expf(ls) + EPSV) * noise_z[b * DDIM + t];
    }
    CP_WAIT(1);
    __syncthreads();                       // stg0 ready, zc ready
    convert(0);
    if (t < 256) {                         // bias for all 256 o rows
        float acc = 0.f;
        const float* wz = W + (long)t * 384 + CIN;
        #pragma unroll
        for (int dd = 0; dd < DDIM; dd += 4) {
            float4 wv = *(const float4*)(wz + dd);
            acc += wv.x * zc[dd] + wv.y * zc[dd + 1] + wv.z * zc[dd + 2] + wv.w * zc[dd + 3];
        }
        sbias[t] = acc + pb[t];
    }
    load_w(1);
    __syncthreads();                       // pane0 ready

    float c[4][4][4];
    #pragma unroll
    for (int i = 0; i < 4; i++)
        #pragma unroll
        for (int j = 0; j < 4; j++)
            #pragma unroll
            for (int k = 0; k < 4; k++) c[i][j][k] = 0.f;

    const int wy = wid >> 2;               // o block (64 rows)
    const int wx = wid & 3;                // p block (32 cols)
    const unsigned r = lane >> 2, qq = lane & 3;
    const unsigned aoff = ((wy * 64 + r) * 20 + qq) * 4;
    const unsigned boff = ((wx * 32 + r) * 20 + qq) * 4;

    for (int ch = 0; ch < NCH; ch++) {
        const int par = ch & 1;
        const unsigned pane = sb + OFF_PANE + par * PANE_BUF;

        // ---- MMA phase on pane[par] ----
        #pragma unroll
        for (int pr = 0; pr < 3; pr++) {
            const unsigned Ab = pane + ((pr == 2) ? PA_LO : PA_HI) + aoff;
            const unsigned Bb = pane + ((pr == 1) ? PB_LO : PB_HI) + boff;
            #pragma unroll
            for (int ks = 0; ks < 2; ks++) {
                unsigned b0[4], b1[4];
                #pragma unroll
                for (int ni = 0; ni < 4; ni++) {
                    unsigned ad = Bb + ks * 32 + ni * 640;
                    b0[ni] = lds32(ad);
                    b1[ni] = lds32(ad + 16);
                }
                #pragma unroll
                for (int mi = 0; mi < 4; mi++) {
                    unsigned aad = Ab + ks * 32 + mi * 1280;
                    unsigned a0 = lds32(aad);
                    unsigned a1 = lds32(aad + 640);
                    unsigned a2 = lds32(aad + 16);
                    unsigned a3 = lds32(aad + 656);
                    #pragma unroll
                    for (int ni = 0; ni < 4; ni++)
                        mma_bf16(c[mi][ni], a0, a1, a2, a3, b0[ni], b1[ni]);
                }
            }
        }

        // ---- prepare chunk ch+1 in pane[par^1]; single barrier per iter ----
        if (ch < NCH - 1) {
            CP_WAIT(0);                    // stg[par^1] (chunk ch+1) landed
            convert(par ^ 1);              // safe: readers of pane[par^1] done pre-prev sync
            if (ch < NCH - 2) {
                load_w(ch + 2);
                issue_f(ch + 2, par);      // stg[par] free (read before prev sync)
            }
            __syncthreads();
        }
    }

    // ---- epilogue: bias add + store ----
    #pragma unroll
    for (int mi = 0; mi < 4; mi++) {
        #pragma unroll
        for (int h = 0; h < 2; h++) {
            int o = wy * 64 + mi * 16 + h * 8 + (int)r;
            float bias = sbias[o];
            float* row = out + ((long)(b * CIN + o)) * HW + p0 + wx * 32 + 2 * qq;
            #pragma unroll
            for (int ni = 0; ni < 4; ni++) {
                float2 v = make_float2(c[mi][ni][2 * h] + bias,
                                       c[mi][ni][2 * h + 1] + bias);
                *(float2*)(row + ni * 8) = v;
            }
        }
    }
}

// ---------------------------------------------------------------------------
extern "C" void kernel_launch(void* const* d_in, const int* in_sizes, int n_in,
                              void* d_out, int out_size)
{
    const float* f_curr   = (const float*)d_in[0];
    const float* mu_prior = (const float*)d_in[1];
    const float* ls_prior = (const float*)d_in[2];
    const float* pi_prior = (const float*)d_in[3];
    const float* mu_post  = (const float*)d_in[4];
    const float* ls_post  = (const float*)d_in[5];
    const float* noise_c  = (const float*)d_in[6];
    const float* noise_z  = (const float*)d_in[7];
    const float* W        = (const float*)d_in[8];
    const float* pb       = (const float*)d_in[9];
    float* out = (float*)d_out;

    cudaFuncSetAttribute(fused_kernel,
                         cudaFuncAttributeMaxDynamicSharedMemorySize, SMEM_TOTAL);
    fused_kernel<<<GEMM_BLKS + BATCH, 512, SMEM_TOTAL>>>(
        f_curr, mu_prior, ls_prior, pi_prior, mu_post, ls_post,
        noise_c, noise_z, W, pb, out, out_size);
}

// round 10
// speedup vs baseline: 1.6062x; 1.4345x over previous
#include <cuda_runtime.h>

#define BATCH 16
#define CIN   256
#define HW    4096
#define DDIM  128
#define CCL   32
#define EPSV  1e-8f
#define NF    ((long)BATCH * CIN * HW)

#define KC    32
#define NCH   8
#define NKLD  16          // KLD blocks come first
#define GEMM_BLKS 512

// ---- smem layout (bytes) ----
// A pane: 256 rows x 144B (32 f32 + 16B pad)  -> conflict-free frag loads
// B pane: 32 rows  x 544B (128 f32 + 16B pad)
#define PANEA_SZ 36864
#define PANEB_SZ 17408
#define OFF_PA   0
#define OFF_PB   73728
#define OFF_ZC   108544
#define OFF_BIAS 109056
#define SMEM_TOTAL 110080

__device__ float g_kld[BATCH];
__device__ int   g_cnt;

// ---------------------------------------------------------------------------
__device__ __forceinline__ unsigned smem_u32(const void* p) {
    unsigned a;
    asm("{ .reg .u64 t; cvta.to.shared.u64 t, %1; cvt.u32.u64 %0, t; }" : "=r"(a) : "l"(p));
    return a;
}
__device__ __forceinline__ void cp16(unsigned dst, const void* src) {
    asm volatile("cp.async.cg.shared.global [%0], [%1], 16;" :: "r"(dst), "l"(src));
}
#define CP_COMMIT() asm volatile("cp.async.commit_group;")
#define CP_WAIT(n)  asm volatile("cp.async.wait_group %0;" :: "n"(n))

__device__ __forceinline__ unsigned lds32(unsigned a) {
    unsigned v;
    asm volatile("ld.shared.b32 %0, [%1];" : "=r"(v) : "r"(a));
    return v;
}

__device__ __forceinline__ void mma_tf32(float* c, unsigned a0, unsigned a1,
                                         unsigned a2, unsigned a3,
                                         unsigned b0, unsigned b1) {
    asm volatile(
        "mma.sync.aligned.m16n8k8.row.col.f32.tf32.tf32.f32 "
        "{%0,%1,%2,%3}, {%4,%5,%6,%7}, {%8,%9}, {%0,%1,%2,%3};"
        : "+f"(c[0]), "+f"(c[1]), "+f"(c[2]), "+f"(c[3])
        : "r"(a0), "r"(a1), "r"(a2), "r"(a3), "r"(b0), "r"(b1));
}

// ---------------------------------------------------------------------------
// Fused kernel: blocks 0..15 KLD, blocks 16..527 GEMM tiles.
// ---------------------------------------------------------------------------
__global__ __launch_bounds__(512, 1)
void fused_kernel(const float* __restrict__ f,  const float* __restrict__ mu_prior,
                  const float* __restrict__ ls_prior, const float* __restrict__ pi_prior,
                  const float* __restrict__ mu_post,  const float* __restrict__ ls_post,
                  const float* __restrict__ noise_c,  const float* __restrict__ noise_z,
                  const float* __restrict__ W,        const float* __restrict__ pb,
                  float* __restrict__ out, int out_size)
{
    extern __shared__ __align__(16) char smem[];
    const int t = threadIdx.x;
    const int wid = t >> 5, lane = t & 31;

    if (blockIdx.x < NKLD) {
        // ------------------------- KLD blocks -------------------------
        const int b = blockIdx.x;
        float* S = (float*)smem;
        float* zpost = S;        float* mupo = S + 128;  float* lspo = S + 256;
        float* e2po  = S + 384;  float* kstd = S + 512;
        float* lps   = S + 640;  float* klgs = S + 896;
        if (t < DDIM) {
            float mu = mu_post[b * DDIM + t];
            float ls = ls_post[b * DDIM + t];
            float e  = expf(ls);
            mupo[t] = mu; lspo[t] = ls; e2po[t] = e * e;
            zpost[t] = mu + e * noise_c[b * DDIM + t];
            kstd[t]  = -ls + 0.5f * (e * e + mu * mu) - 0.5f;
        }
        __syncthreads();
        const int c = lane;
        if (wid < 8) {
            float lp = 0.f, klg = 0.f;
            #pragma unroll 4
            for (int j = 0; j < 16; j++) {
                int dd = wid * 16 + j;
                long idx = ((long)b * DDIM + dd) * CCL + c;
                float mpr = mu_prior[idx];
                float lpr = ls_prior[idx];
                float s2x2 = 2.f * expf(2.f * lpr);
                float dz = zpost[dd] - mpr;
                lp += -lpr - 0.91893853320467274f - dz * dz / s2x2;
                float dm = mupo[dd] - mpr;
                klg += lpr - lspo[dd] + (e2po[dd] + dm * dm) / (s2x2 + EPSV) - 0.5f;
            }
            lps[wid * 32 + c] = lp; klgs[wid * 32 + c] = klg;
        }
        __syncthreads();
        if (wid == 0) {
            float LP = 0.f, KG = 0.f;
            #pragma unroll
            for (int j = 0; j < 8; j++) { LP += lps[j * 32 + c]; KG += klgs[j * 32 + c]; }
            float m = LP;
            #pragma unroll
            for (int o = 16; o; o >>= 1) m = fmaxf(m, __shfl_xor_sync(~0u, m, o));
            float e = expf(LP - m), s = e;
            #pragma unroll
            for (int o = 16; o; o >>= 1) s += __shfl_xor_sync(~0u, s, o);
            float pi = e / s;
            float term = pi * KG + pi * (logf(pi + EPSV) - logf(pi_prior[b * CCL + c] + EPSV));
            #pragma unroll
            for (int o = 16; o; o >>= 1) term += __shfl_xor_sync(~0u, term, o);
            float ks = kstd[c] + kstd[c + 32] + kstd[c + 64] + kstd[c + 96];
            #pragma unroll
            for (int o = 16; o; o >>= 1) ks += __shfl_xor_sync(~0u, ks, o);
            if (c == 0) g_kld[b] = term + ks;
        }
        __syncthreads();
        if (t == 0) {
            __threadfence();
            int old = atomicAdd(&g_cnt, 1);
            if (old == BATCH - 1) {
                __threadfence();
                float s = 0.f;
                #pragma unroll
                for (int bb = 0; bb < BATCH; bb++) s += g_kld[bb];
                s *= (1.f / BATCH);
                for (long i = NF; i < (long)out_size; i++) out[i] = s;
                atomicExch(&g_cnt, 0);
            }
        }
        return;
    }

    // ------------------------------ GEMM blocks ------------------------------
    const int gbid = blockIdx.x - NKLD;
    const int b  = gbid >> 5;
    const int p0 = (gbid & 31) << 7;
    const unsigned sb = smem_u32(smem);
    float* zc    = (float*)(smem + OFF_ZC);
    float* sbias = (float*)(smem + OFF_BIAS);

    const float* fb = f + (long)b * CIN * HW + p0;

    // cp.async a full chunk straight into operand panes (native orientation)
    auto issue = [&](int ch, int par) {
        // W chunk: 256 rows x 32 f32, pitch 144B
        unsigned pa = sb + OFF_PA + par * PANEA_SZ;
        #pragma unroll
        for (int j = 0; j < 4; j++) {
            int id = t + j * 512, row = id >> 3, seg = id & 7;
            cp16(pa + row * 144 + seg * 16, W + (long)row * 384 + ch * KC + seg * 4);
        }
        // f chunk: 32 rows x 128 f32, pitch 544B
        unsigned pbn = sb + OFF_PB + par * PANEB_SZ;
        #pragma unroll
        for (int j = 0; j < 2; j++) {
            int id = t + j * 512, row = id >> 5, seg = id & 31;
            cp16(pbn + row * 544 + seg * 16, fb + (long)(ch * KC + row) * HW + seg * 4);
        }
        CP_COMMIT();
    };

    // ---- prologue ----
    issue(0, 0);
    issue(1, 1);
    if (t < DDIM) {
        float mu = mu_post[b * DDIM + t];
        float ls = ls_post[b * DDIM + t];
        zc[t] = mu + (expf(ls) + EPSV) * noise_z[b * DDIM + t];
    }
    CP_WAIT(1);
    __syncthreads();                  // pane0 + zc visible
    if (t < 256) {
        float acc = 0.f;
        const float* wz = W + (long)t * 384 + CIN;
        #pragma unroll
        for (int dd = 0; dd < DDIM; dd += 4) {
            float4 wv = *(const float4*)(wz + dd);
            acc += wv.x * zc[dd] + wv.y * zc[dd + 1] + wv.z * zc[dd + 2] + wv.w * zc[dd + 3];
        }
        sbias[t] = acc + pb[t];
    }

    float c[4][4][4];
    #pragma unroll
    for (int i = 0; i < 4; i++)
        #pragma unroll
        for (int j = 0; j < 4; j++)
            #pragma unroll
            for (int k = 0; k < 4; k++) c[i][j][k] = 0.f;

    const int wy = wid >> 2;          // o block (64 rows)
    const int wx = wid & 3;           // p block (32 cols)
    const unsigned r = lane >> 2, qq = lane & 3;
    // A: addr = (wy*64 + mi*16 + r)*144 + (ks*8 + qq)*4   (+1152 row+8, +16 col+4)
    const unsigned abase = (wy * 64 + r) * 144 + qq * 4;
    // B: addr = (ks*8 + qq)*544 + (wx*32 + ni*8 + r)*4    (+2176 row+4)
    const unsigned bbase = qq * 544 + (wx * 32 + r) * 4;

    for (int ch = 0; ch < NCH; ch++) {
        const int par = ch & 1;
        const unsigned pa = sb + OFF_PA + par * PANEA_SZ;
        const unsigned pbn = sb + OFF_PB + par * PANEB_SZ;

        #pragma unroll
        for (int ks = 0; ks < 4; ks++) {
            unsigned b0[4], b1[4];
            #pragma unroll
            for (int ni = 0; ni < 4; ni++) {
                unsigned ad = pbn + bbase + ks * 8 * 544 + ni * 32;
                b0[ni] = lds32(ad);
                b1[ni] = lds32(ad + 2176);
            }
            #pragma unroll
            for (int mi = 0; mi < 4; mi++) {
                unsigned aad = pa + abase + mi * 16 * 144 + ks * 32;
                unsigned a0 = lds32(aad);
                unsigned a1 = lds32(aad + 1152);
                unsigned a2 = lds32(aad + 16);
                unsigned a3 = lds32(aad + 1168);
                #pragma unroll
                for (int ni = 0; ni < 4; ni++)
                    mma_tf32(c[mi][ni], a0, a1, a2, a3, b0[ni], b1[ni]);
            }
        }

        if (ch < NCH - 1) {
            CP_WAIT(0);               // chunk ch+1 landed
            __syncthreads();          // all warps done with pane[par]
            if (ch < NCH - 2) issue(ch + 2, par);
        }
    }

    // ---- epilogue: bias add + store ----
    #pragma unroll
    for (int mi = 0; mi < 4; mi++) {
        #pragma unroll
        for (int h = 0; h < 2; h++) {
            int o = wy * 64 + mi * 16 + h * 8 + (int)r;
            float bias = sbias[o];
            float* row = out + ((long)(b * CIN + o)) * HW + p0 + wx * 32 + 2 * qq;
            #pragma unroll
            for (int ni = 0; ni < 4; ni++) {
                float2 v = make_float2(c[mi][ni][2 * h] + bias,
                                       c[mi][ni][2 * h + 1] + bias);
                *(float2*)(row + ni * 8) = v;
            }
        }
    }
}

// ---------------------------------------------------------------------------
extern "C" void kernel_launch(void* const* d_in, const int* in_sizes, int n_in,
                              void* d_out, int out_size)
{
    const float* f_curr   = (const float*)d_in[0];
    const float* mu_prior = (const float*)d_in[1];
    const float* ls_prior = (const float*)d_in[2];
    const float* pi_prior = (const float*)d_in[3];
    const float* mu_post  = (const float*)d_in[4];
    const float* ls_post  = (const float*)d_in[5];
    const float* noise_c  = (const float*)d_in[6];
    const float* noise_z  = (const float*)d_in[7];
    const float* W        = (const float*)d_in[8];
    const float* pb       = (const float*)d_in[9];
    float* out = (float*)d_out;

    cudaFuncSetAttribute(fused_kernel,
                         cudaFuncAttributeMaxDynamicSharedMemorySize, SMEM_TOTAL);
    fused_kernel<<<NKLD + GEMM_BLKS, 512, SMEM_TOTAL>>>(
        f_curr, mu_prior, ls_prior, pi_prior, mu_post, ls_post,
        noise_c, noise_z, W, pb, out, out_size);
}